// round 3
// baseline (speedup 1.0000x reference)
#include <cuda_runtime.h>
#include <cuda_bf16.h>
#include <math.h>
#include <cstdint>

#define NB      4096
#define PAD     (NB / 2)
#define BATCH   8192
#define T_MAIN  1024
#define NWARP   (T_MAIN / 32)      // 32
#define GRID_MAIN 304              // 152 SMs * 2 CTAs/SM (GB300)

// Row-invariant precomputed data: interleaved {p = sigmoid(l), l} pairs, and
// C = sum_j log_sigmoid(-l_j).
__device__ float2 g_pl[NB];
__device__ float  g_C;

// ---------------------------------------------------------------------------
// Precompute: single block. p = sigmoid(logits), C = sum log_sigmoid(-l).
// ---------------------------------------------------------------------------
__global__ __launch_bounds__(1024)
void precompute_kernel(const float* __restrict__ logits) {
    __shared__ float s_red[32];
    const int tid = threadIdx.x;
    float acc = 0.0f;

    #pragma unroll
    for (int j = tid; j < NB; j += 1024) {
        float l = logits[j];
        g_pl[j] = make_float2(1.0f / (1.0f + expf(-l)), l);
        // log_sigmoid(-l) = -(log1p(exp(-|l|)) + max(l,0))   (stable)
        float a = fabsf(l);
        acc -= log1pf(expf(-a)) + fmaxf(l, 0.0f);
    }
    #pragma unroll
    for (int o = 16; o; o >>= 1) acc += __shfl_xor_sync(0xFFFFFFFFu, acc, o);
    if ((tid & 31) == 0) s_red[tid >> 5] = acc;
    __syncthreads();
    if (tid < 32) {
        float v = s_red[tid];
        #pragma unroll
        for (int o = 16; o; o >>= 1) v += __shfl_xor_sync(0xFFFFFFFFu, v, o);
        if (tid == 0) g_C = v;
    }
}

// ---------------------------------------------------------------------------
// Persistent fused kernel. 1024 threads, 2 CTAs/SM, 4 elems/thread.
//  - {p,l} pairs live in 8 registers for the whole kernel (loaded once).
//  - grid stored as bytes in double-buffered smem (4KB/buffer).
//  - one __syncthreads per row; next-row u prefetched before the gather.
//  - gather: 2x LDS.32 + byte_perm + IMAD bit-trick -> one STG.128.
// ---------------------------------------------------------------------------
__global__ __launch_bounds__(T_MAIN, 2)
void fused_kernel(const float* __restrict__ u,
                  const int*   __restrict__ shift,
                  float*       __restrict__ masks,
                  float*       __restrict__ log_probs) {
    __shared__ __align__(16) unsigned char s_g[2][NB + 16];
    __shared__ float s_red[2][NWARP];

    const int tid  = threadIdx.x;
    const int lane = tid & 31;
    const int warp = tid >> 5;

    // Row-invariant {p,l} pairs for this thread's 4 elements (e = 4*tid..4*tid+3)
    const float4* pl4 = (const float4*)g_pl;
    const float4 q0 = pl4[2 * tid];      // p0,l0,p1,l1
    const float4 q1 = pl4[2 * tid + 1];  // p2,l2,p3,l3
    const float  cC = g_C;

    int b   = blockIdx.x;
    int buf = 0;

    // preload first row
    float4 uu = ((const float4*)(u + (size_t)b * NB))[tid];
    int    sh = shift[b];

    while (b < BATCH) {
        // ---- compute grid bits + weighted sum -------------------------------
        uint32_t w = (uu.x < q0.x ? 0x01u       : 0u)
                   | (uu.y < q0.z ? 0x100u      : 0u)
                   | (uu.z < q1.x ? 0x10000u    : 0u)
                   | (uu.w < q1.z ? 0x1000000u  : 0u);
        float acc = (uu.x < q0.x ? q0.y : 0.0f)
                  + (uu.y < q0.z ? q0.w : 0.0f)
                  + (uu.z < q1.x ? q1.y : 0.0f)
                  + (uu.w < q1.z ? q1.w : 0.0f);
        *(uint32_t*)&s_g[buf][4 * tid] = w;

        // ---- block reduction -> log_probs[b] --------------------------------
        #pragma unroll
        for (int o = 16; o; o >>= 1) acc += __shfl_xor_sync(0xFFFFFFFFu, acc, o);
        if (lane == 0) s_red[buf][warp] = acc;
        __syncthreads();
        if (warp == 0) {
            float v = s_red[buf][lane];  // NWARP == 32 exactly
            #pragma unroll
            for (int o = 16; o; o >>= 1) v += __shfl_xor_sync(0xFFFFFFFFu, v, o);
            if (lane == 0) log_probs[b] = v + cC;
        }

        // ---- prefetch next row (in flight during gather/store) --------------
        float* __restrict__ out = masks + (size_t)b * NB;
        const int curSh = sh;
        const int bn = b + GRID_MAIN;
        if (bn < BATCH) {
            uu = ((const float4*)(u + (size_t)bn * NB))[tid];
            sh = shift[bn];
        }

        // ---- reflect-shift gather -> one float4 store -----------------------
        const uint32_t* sw = (const uint32_t*)&s_g[buf][0];
        const int base = curSh + 4 * tid - PAD;   // output elems 4*tid..4*tid+3
        float4 o4;
        if (base >= 0 && base <= NB - 4) {
            // fast path: 4 consecutive bytes, possibly straddling 2 words
            const int wi = base >> 2;
            uint32_t w0 = sw[wi], w1 = sw[wi + 1];           // wi+1 stays in padding
            uint32_t pk = __byte_perm(w0, w1, 0x3210 + (base & 3) * 0x1111);
            o4.x = __int_as_float((pk & 0xFFu)          * 0x3F800000u);
            o4.y = __int_as_float(((pk >> 8)  & 0xFFu)  * 0x3F800000u);
            o4.z = __int_as_float(((pk >> 16) & 0xFFu)  * 0x3F800000u);
            o4.w = __int_as_float(((pk >> 24) & 0xFFu)  * 0x3F800000u);
        } else {
            // slow path: reflect each index (only edge warps hit this)
            float r[4];
            #pragma unroll
            for (int k = 0; k < 4; k++) {
                int s = base + k;
                s = (s < 0) ? -s : s;
                s = (s >= NB) ? (2 * (NB - 1) - s) : s;
                r[k] = (float)s_g[buf][s];
            }
            o4 = make_float4(r[0], r[1], r[2], r[3]);
        }
        ((float4*)out)[tid] = o4;

        buf ^= 1;
        b = bn;
    }
}

// ---------------------------------------------------------------------------
extern "C" void kernel_launch(void* const* d_in, const int* in_sizes, int n_in,
                              void* d_out, int out_size) {
    const float* logits = (const float*)d_in[0];   // (NB,)
    const float* u      = (const float*)d_in[1];   // (B, NB)
    const int*   shift  = (const int*)  d_in[2];   // (B,)

    float* masks     = (float*)d_out;                       // (B, 1, NB)
    float* log_probs = (float*)d_out + (size_t)BATCH * NB;  // (B,)

    precompute_kernel<<<1, 1024>>>(logits);
    fused_kernel<<<GRID_MAIN, T_MAIN>>>(u, shift, masks, log_probs);
}

// round 4
// speedup vs baseline: 1.1580x; 1.1580x over previous
#include <cuda_runtime.h>
#include <cuda_bf16.h>
#include <math.h>
#include <cstdint>

#define NB      4096
#define PAD     (NB / 2)
#define BATCH   8192
#define T       512
#define NWARP   (T / 32)          // 16
#define GRID_N  592               // 148 SMs * 4 CTAs/SM

// Row-invariant precomputed data.
__device__ float          g_p[NB];    // sigmoid(logits)
__device__ __nv_bfloat16  g_lb[NB];   // logits (bf16, used only for the weighted sum)
__device__ float          g_C;        // sum_j log_sigmoid(-logits[j])

// ---------------------------------------------------------------------------
// Precompute: single block.
// ---------------------------------------------------------------------------
__global__ __launch_bounds__(1024)
void precompute_kernel(const float* __restrict__ logits) {
    __shared__ float s_red[32];
    const int tid = threadIdx.x;
    float acc = 0.0f;

    #pragma unroll
    for (int j = tid; j < NB; j += 1024) {
        float l = logits[j];
        g_p[j]  = 1.0f / (1.0f + expf(-l));
        g_lb[j] = __float2bfloat16(l);
        float a = fabsf(l);                       // log_sigmoid(-l), stable
        acc -= log1pf(expf(-a)) + fmaxf(l, 0.0f);
    }
    #pragma unroll
    for (int o = 16; o; o >>= 1) acc += __shfl_xor_sync(0xFFFFFFFFu, acc, o);
    if ((tid & 31) == 0) s_red[tid >> 5] = acc;
    __syncthreads();
    if (tid < 32) {
        float v = s_red[tid];
        #pragma unroll
        for (int o = 16; o; o >>= 1) v += __shfl_xor_sync(0xFFFFFFFFu, v, o);
        if (tid == 0) g_C = v;
    }
}

// ---------------------------------------------------------------------------
// Fused kernel: grid-stride, 512 threads, 4 CTAs/SM, 8 elems/thread (MLP=2).
// Byte-packed grid in double-buffered smem; one barrier per row.
// ---------------------------------------------------------------------------
__global__ __launch_bounds__(T, 4)
void fused_kernel(const float* __restrict__ u,
                  const int*   __restrict__ shift,
                  float*       __restrict__ masks,
                  float*       __restrict__ log_probs) {
    __shared__ __align__(16) unsigned char s_g[2][NB + 16];
    __shared__ float s_red[2][NWARP];

    const int tid  = threadIdx.x;
    const int lane = tid & 31;
    const int warp = tid >> 5;

    const float4* __restrict__ p4  = (const float4*)g_p;
    const uint2*  __restrict__ lb2 = (const uint2*)g_lb;   // 4 bf16 per uint2

    int buf = 0;
    for (int b = blockIdx.x; b < BATCH; b += GRID_N, buf ^= 1) {
        const float4* __restrict__ u4 = (const float4*)(u + (size_t)b * NB);

        // ---- load (both iterations issued up front: MLP=2 on DRAM) ---------
        float4 ua = __ldcs(&u4[tid]);
        float4 ub = __ldcs(&u4[tid + T]);
        float4 pa = p4[tid];
        float4 pb = p4[tid + T];
        uint2  la = lb2[tid];
        uint2  lb = lb2[tid + T];

        __nv_bfloat162 la0 = *reinterpret_cast<__nv_bfloat162*>(&la.x);
        __nv_bfloat162 la1 = *reinterpret_cast<__nv_bfloat162*>(&la.y);
        __nv_bfloat162 lb0 = *reinterpret_cast<__nv_bfloat162*>(&lb.x);
        __nv_bfloat162 lb1 = *reinterpret_cast<__nv_bfloat162*>(&lb.y);

        // ---- grid bits + weighted sum ---------------------------------------
        uint32_t wa = (ua.x < pa.x ? 0x01u      : 0u)
                    | (ua.y < pa.y ? 0x100u     : 0u)
                    | (ua.z < pa.z ? 0x10000u   : 0u)
                    | (ua.w < pa.w ? 0x1000000u : 0u);
        uint32_t wb = (ub.x < pb.x ? 0x01u      : 0u)
                    | (ub.y < pb.y ? 0x100u     : 0u)
                    | (ub.z < pb.z ? 0x10000u   : 0u)
                    | (ub.w < pb.w ? 0x1000000u : 0u);
        float acc = (ua.x < pa.x ? __low2float(la0)  : 0.0f)
                  + (ua.y < pa.y ? __high2float(la0) : 0.0f)
                  + (ua.z < pa.z ? __low2float(la1)  : 0.0f)
                  + (ua.w < pa.w ? __high2float(la1) : 0.0f)
                  + (ub.x < pb.x ? __low2float(lb0)  : 0.0f)
                  + (ub.y < pb.y ? __high2float(lb0) : 0.0f)
                  + (ub.z < pb.z ? __low2float(lb1)  : 0.0f)
                  + (ub.w < pb.w ? __high2float(lb1) : 0.0f);

        uint32_t* sw = (uint32_t*)&s_g[buf][0];
        sw[tid]     = wa;
        sw[tid + T] = wb;

        // ---- block reduction -> log_probs[b] --------------------------------
        #pragma unroll
        for (int o = 16; o; o >>= 1) acc += __shfl_xor_sync(0xFFFFFFFFu, acc, o);
        if (lane == 0) s_red[buf][warp] = acc;
        __syncthreads();
        if (warp == 0) {
            float v = (lane < NWARP) ? s_red[buf][lane] : 0.0f;
            #pragma unroll
            for (int o = 8; o; o >>= 1) v += __shfl_xor_sync(0xFFFFFFFFu, v, o);
            if (lane == 0) log_probs[b] = v + g_C;
        }

        // ---- reflect-shift gather -> 2x STG.128 ------------------------------
        const int sh = shift[b];
        float4* __restrict__ out4 = (float4*)(masks + (size_t)b * NB);

        #pragma unroll
        for (int it = 0; it < 2; ++it) {
            const int j0   = 4 * (tid + it * T);
            const int base = sh + j0 - PAD;
            float4 o4;
            if (base >= 0 && base <= NB - 4) {
                const int wi = base >> 2;
                uint32_t w0 = sw[wi], w1 = sw[wi + 1];        // wi+1 within padding
                uint32_t pk = __byte_perm(w0, w1, 0x3210 + (base & 3) * 0x1111);
                o4.x = __int_as_float((pk & 0xFFu)         * 0x3F800000u);
                o4.y = __int_as_float(((pk >> 8)  & 0xFFu) * 0x3F800000u);
                o4.z = __int_as_float(((pk >> 16) & 0xFFu) * 0x3F800000u);
                o4.w = __int_as_float(((pk >> 24) & 0xFFu) * 0x3F800000u);
            } else {
                float r[4];
                #pragma unroll
                for (int k = 0; k < 4; k++) {
                    int s = base + k;
                    s = (s < 0) ? -s : s;
                    s = (s >= NB) ? (2 * (NB - 1) - s) : s;
                    r[k] = (float)s_g[buf][s];
                }
                o4 = make_float4(r[0], r[1], r[2], r[3]);
            }
            __stcs(&out4[tid + it * T], o4);
        }
        // double buffer: next row's writes go to the other buffer, so the
        // single __syncthreads above is the only barrier needed per row.
    }
}

// ---------------------------------------------------------------------------
extern "C" void kernel_launch(void* const* d_in, const int* in_sizes, int n_in,
                              void* d_out, int out_size) {
    const float* logits = (const float*)d_in[0];   // (NB,)
    const float* u      = (const float*)d_in[1];   // (B, NB)
    const int*   shift  = (const int*)  d_in[2];   // (B,)

    float* masks     = (float*)d_out;                       // (B, 1, NB)
    float* log_probs = (float*)d_out + (size_t)BATCH * NB;  // (B,)

    precompute_kernel<<<1, 1024>>>(logits);
    fused_kernel<<<GRID_N, T>>>(u, shift, masks, log_probs);
}